// round 15
// baseline (speedup 1.0000x reference)
#include <cuda_runtime.h>
#include <cuda_fp16.h>
#include <cstdint>

#define BB 4
#define NN 2048
#define DD 1024
#define HH 16
#define DHH 64
#define MROWS (BB * NN)   // 8192

// ---------------- scratch (device globals; no runtime allocation) ----------
__device__ __half g_xn[(size_t)MROWS * DD];   // fp16 LN output
__device__ __half g_q [(size_t)MROWS * DD];   // [b,h,n,dh], pre-scaled by 0.125*lg2e
__device__ __half g_k [(size_t)MROWS * DD];   // [b,h,n,dh]
__device__ __half g_v [(size_t)MROWS * DD];   // [b,h,dh,n]  (TRANSPOSED)
__device__ __half g_ao[(size_t)MROWS * DD];   // [b,n,(h dh)]
__device__ __half g_wt [(size_t)3072 * DD];   // [Wq|Wkv]^T rows n, fp16 (Wq part scaled)
__device__ __half g_wot[(size_t)DD * DD];     // Wo^T, fp16

#define QSCALE 0.18033688f   // 0.125 * log2(e)

// ---------------- PTX helpers ----------------------------------------------
__device__ __forceinline__ float ex2f(float x) {
    float y;
    asm("ex2.approx.ftz.f32 %0, %1;" : "=f"(y) : "f"(x));
    return y;
}
__device__ __forceinline__ uint32_t h2pack(float lo, float hi) {
    __half2 h = __floats2half2_rn(lo, hi);
    return *(uint32_t*)&h;
}
__device__ __forceinline__ void mma_f16(float* d, const uint32_t* a,
                                        uint32_t b0, uint32_t b1) {
    asm volatile(
        "mma.sync.aligned.m16n8k16.row.col.f32.f16.f16.f32 "
        "{%0,%1,%2,%3},{%4,%5,%6,%7},{%8,%9},{%0,%1,%2,%3};\n"
        : "+f"(d[0]), "+f"(d[1]), "+f"(d[2]), "+f"(d[3])
        : "r"(a[0]), "r"(a[1]), "r"(a[2]), "r"(a[3]), "r"(b0), "r"(b1));
}
__device__ __forceinline__ void ldsm4(uint32_t& r0, uint32_t& r1, uint32_t& r2,
                                      uint32_t& r3, uint32_t addr) {
    asm volatile("ldmatrix.sync.aligned.m8n8.x4.shared.b16 {%0,%1,%2,%3}, [%4];"
                 : "=r"(r0), "=r"(r1), "=r"(r2), "=r"(r3) : "r"(addr));
}
__device__ __forceinline__ void cp16(uint32_t dst, const void* src) {
    asm volatile("cp.async.cg.shared.global [%0], [%1], 16;\n" :: "r"(dst), "l"(src));
}
__device__ __forceinline__ void cp_commit() {
    asm volatile("cp.async.commit_group;\n" ::);
}

// ============================================================================
// Fused prep v2: blocks 0..1023 transpose 64x64 weight tiles (vectorized);
// blocks 1024..2047 LayerNorm (warp per row).
// ============================================================================
__global__ __launch_bounds__(256) void prep_kernel(const float* __restrict__ x,
                                                   const float* __restrict__ gamma,
                                                   const float* __restrict__ wq,
                                                   const float* __restrict__ wkv,
                                                   const float* __restrict__ wo) {
    const int bid = blockIdx.x;
    if (bid < 1024) {
        __shared__ float ts[64][65];
        const float* S; __half* D; int Nn, rowbase, ti; float scale;
        if (bid < 256)      { S = wq;  D = g_wt;  Nn = 1024; rowbase = 0;    ti = bid;       scale = QSCALE; }
        else if (bid < 768) { S = wkv; D = g_wt;  Nn = 2048; rowbase = 1024; ti = bid - 256; scale = 1.0f; }
        else                { S = wo;  D = g_wot; Nn = 1024; rowbase = 0;    ti = bid - 768; scale = 1.0f; }
        const int nt = Nn / 64;
        const int k0 = (ti / nt) * 64, n0 = (ti % nt) * 64;
        const int tid = threadIdx.x;
        {
            const int rl = tid >> 4, c4 = (tid & 15) << 2;
            #pragma unroll
            for (int i = 0; i < 4; i++) {
                const int row = rl + i * 16;
                float4 v = *(const float4*)&S[(size_t)(k0 + row) * Nn + n0 + c4];
                ts[row][c4 + 0] = v.x * scale;
                ts[row][c4 + 1] = v.y * scale;
                ts[row][c4 + 2] = v.z * scale;
                ts[row][c4 + 3] = v.w * scale;
            }
        }
        __syncthreads();
        {
            const int nr = tid >> 2, kc = (tid & 3) * 16;
            uint32_t p[8];
            #pragma unroll
            for (int j = 0; j < 8; j++)
                p[j] = h2pack(ts[kc + 2 * j][nr], ts[kc + 2 * j + 1][nr]);
            __half* dst = D + (size_t)(rowbase + n0 + nr) * DD + k0 + kc;
            *(uint4*)dst       = make_uint4(p[0], p[1], p[2], p[3]);
            *(uint4*)(dst + 8) = make_uint4(p[4], p[5], p[6], p[7]);
        }
    } else {
        const int wid = threadIdx.x >> 5, lane = threadIdx.x & 31;
        const int row = (bid - 1024) * 8 + wid;
        const float4* xr = (const float4*)(x + (size_t)row * DD);
        const float4* gr = (const float4*)gamma;
        float4 v[8];
        float s = 0.f, ss = 0.f;
        #pragma unroll
        for (int j = 0; j < 8; j++) {
            v[j] = xr[lane + j * 32];
            s  += v[j].x + v[j].y + v[j].z + v[j].w;
            ss += v[j].x*v[j].x + v[j].y*v[j].y + v[j].z*v[j].z + v[j].w*v[j].w;
        }
        #pragma unroll
        for (int off = 16; off > 0; off >>= 1) {
            s  += __shfl_xor_sync(0xffffffffu, s,  off);
            ss += __shfl_xor_sync(0xffffffffu, ss, off);
        }
        const float mu = s * (1.0f / DD);
        const float rstd = rsqrtf(ss * (1.0f / DD) - mu * mu + 1e-5f);
        uint2* orow = (uint2*)(g_xn + (size_t)row * DD);
        #pragma unroll
        for (int j = 0; j < 8; j++) {
            float4 gv = gr[lane + j * 32];
            uint2 o;
            o.x = h2pack((v[j].x - mu) * rstd * gv.x, (v[j].y - mu) * rstd * gv.y);
            o.y = h2pack((v[j].z - mu) * rstd * gv.z, (v[j].w - mu) * rstd * gv.w);
            orow[lane + j * 32] = o;
        }
    }
}

// ============================================================================
// fp16 m16n8k16 GEMM (unchanged): CTA 128x128, 4 warps, warp 64x64,
// 3-stage cp.async, one barrier per k-chunk.
// ============================================================================
#define GT_BYTES 16384
#define GSTAGE_BYTES (2 * GT_BYTES)
#define GEMM_SMEM_BYTES (3 * GSTAGE_BYTES)

template<int MODE>
__global__ __launch_bounds__(128, 2) void gemm_mma(float* __restrict__ C) {
    extern __shared__ char smc[];
    const uint32_t sb = (uint32_t)__cvta_generic_to_shared(smc);

    const __half* A  = (MODE == 0) ? g_xn : g_ao;
    const __half* Bt = (MODE == 0) ? g_wt : g_wot;

    const int m0 = blockIdx.y * 128;
    const int c0 = blockIdx.x * 128;

    const int tid = threadIdx.x;
    const int wid = tid >> 5, lane = tid & 31;
    const int wm = wid & 1;
    const int wn = wid >> 1;

    float acc[4][8][4];
    #pragma unroll
    for (int i = 0; i < 4; i++)
        #pragma unroll
        for (int t = 0; t < 8; t++)
            #pragma unroll
            for (int e = 0; e < 4; e++) acc[i][t][e] = 0.0f;

    const int lrow = tid >> 3, lch = tid & 7;

    auto load_tile = [&](int j, int stage) {
        const int k0 = j * 64;
        const uint32_t ab = sb + (uint32_t)stage * GSTAGE_BYTES;
        const uint32_t bb = ab + GT_BYTES;
        #pragma unroll
        for (int i = 0; i < 8; i++) {
            const int row = lrow + i * 16;
            const uint32_t off = (uint32_t)(row * 128 + (((lch ^ (row & 7)) & 7) << 4));
            cp16(ab + off, &A [(size_t)(m0 + row) * DD + k0 + lch * 8]);
            cp16(bb + off, &Bt[(size_t)(c0 + row) * DD + k0 + lch * 8]);
        }
        cp_commit();
    };

    uint32_t a_rowb[4];
    #pragma unroll
    for (int ig = 0; ig < 4; ig++)
        a_rowb[ig] = (uint32_t)(wm * 64 + ig * 16 + (lane & 15)) * 128;
    const int a_chbit = lane >> 4;
    uint32_t b_rowb[4];
    #pragma unroll
    for (int grp = 0; grp < 4; grp++)
        b_rowb[grp] = (uint32_t)(wn * 64 + grp * 16 + (lane & 7) + ((lane & 16) >> 1)) * 128;
    const int b_chbit = (lane >> 3) & 1;
    const int lxor = lane & 7;

    load_tile(0, 0);
    load_tile(1, 1);

    int cb = 0, nb = 2;
    for (int j = 0; j < 16; j++) {
        if (j < 15) asm volatile("cp.async.wait_group 1;\n" ::);
        else        asm volatile("cp.async.wait_group 0;\n" ::);
        __syncthreads();
        if (j + 2 < 16) {
            load_tile(j + 2, nb);
            nb = (nb == 2) ? 0 : nb + 1;
        }

        const uint32_t ab = sb + (uint32_t)cb * GSTAGE_BYTES;
        const uint32_t bb = ab + GT_BYTES;
        #pragma unroll
        for (int ks = 0; ks < 4; ks++) {
            uint32_t af[4][4];
            const uint32_t axo = (uint32_t)(((2 * ks + a_chbit) ^ lxor) << 4);
            #pragma unroll
            for (int ig = 0; ig < 4; ig++)
                ldsm4(af[ig][0], af[ig][1], af[ig][2], af[ig][3],
                      ab + a_rowb[ig] + axo);
            uint32_t bf[4][4];
            const uint32_t bxo = (uint32_t)(((2 * ks + b_chbit) ^ lxor) << 4);
            #pragma unroll
            for (int grp = 0; grp < 4; grp++)
                ldsm4(bf[grp][0], bf[grp][1], bf[grp][2], bf[grp][3],
                      bb + b_rowb[grp] + bxo);
            #pragma unroll
            for (int ig = 0; ig < 4; ig++)
                #pragma unroll
                for (int t = 0; t < 8; t++)
                    mma_f16(acc[ig][t], af[ig],
                            bf[t >> 1][(t & 1) * 2], bf[t >> 1][(t & 1) * 2 + 1]);
        }
        cb = (cb == 2) ? 0 : cb + 1;
    }

    const int g = lane >> 2, cq = lane & 3;
    #pragma unroll
    for (int ig = 0; ig < 4; ig++) {
        #pragma unroll
        for (int t = 0; t < 8; t++) {
            const int row = m0 + wm * 64 + ig * 16 + g;
            const int col = c0 + wn * 64 + t * 8 + 2 * cq;
            float* d = acc[ig][t];
            if (MODE == 1) {
                *(float2*)&C[(size_t)row * DD + col]       = make_float2(d[0], d[1]);
                *(float2*)&C[(size_t)(row + 8) * DD + col] = make_float2(d[2], d[3]);
            } else {
                const int b = row >> 11, n = row & 2047;
                if (col < 2048) {
                    __half* dst = (col < 1024) ? g_q : g_k;
                    const int cc = col & 1023;
                    const int h = cc >> 6, dh = cc & 63;
                    __half* base = dst + (((size_t)(b * HH + h) * NN) * DHH + dh);
                    *(uint32_t*)&base[(size_t)n * DHH]       = h2pack(d[0], d[1]);
                    *(uint32_t*)&base[(size_t)(n + 8) * DHH] = h2pack(d[2], d[3]);
                } else {
                    const int cc = col - 2048;
                    const int h = cc >> 6, dh = cc & 63;
                    __half* base = g_v + ((size_t)(b * HH + h) * DHH + dh) * NN;
                    base[n]          = __float2half_rn(d[0]);
                    base[NN + n]     = __float2half_rn(d[1]);
                    base[n + 8]      = __float2half_rn(d[2]);
                    base[NN + n + 8] = __float2half_rn(d[3]);
                }
            }
        }
    }
}

// ============================================================================
// Causal flash attention fp16 v7: KV-PAIR pipeline stages. 2 stages, each
// holds TWO 64-row KV sub-tiles -> ONE barrier per 2 tiles (tiles/CTA is
// always even: 2qt+2). 4 warps x 32 q-rows, 128 threads, 2 CTAs/SM.
// ============================================================================
#define AKST 72
#define SUB_B (64 * AKST * 2)            // one K or V sub-tile = 9216 B
#define ASTG_B (4 * SUB_B)               // stage = K0 K1 V0 V1 = 36864 B
#define ATTN_SMEM_BYTES (2 * ASTG_B)     // 73728 B

__global__ __launch_bounds__(128, 2) void attn_kernel() {
    extern __shared__ char smc[];
    const uint32_t sbase = (uint32_t)__cvta_generic_to_shared(smc);

    const int bh = blockIdx.x;                              // 0..63
    const int qt = (int)gridDim.y - 1 - (int)blockIdx.y;    // heavy first
    const int tid = threadIdx.x;
    const int w = tid >> 5;
    const int lane = tid & 31;
    const int g = lane >> 2;
    const int c = lane & 3;

    const size_t hoff = (size_t)bh * NN * DHH;
    const __half* Qg  = g_q + hoff + (size_t)qt * 128 * DHH;
    const __half* Kg0 = g_k + hoff;
    const __half* Vg0 = g_v + hoff;   // [dh][n]

    uint32_t aQ[2][4][4];
    #pragma unroll
    for (int mi = 0; mi < 2; mi++) {
        const int r0 = w * 32 + mi * 16 + g, r1 = r0 + 8;
        #pragma unroll
        for (int ks = 0; ks < 4; ks++) {
            aQ[mi][ks][0] = *(const uint32_t*)&Qg[r0 * DHH + ks * 16 + 2 * c];
            aQ[mi][ks][1] = *(const uint32_t*)&Qg[r1 * DHH + ks * 16 + 2 * c];
            aQ[mi][ks][2] = *(const uint32_t*)&Qg[r0 * DHH + ks * 16 + 2 * c + 8];
            aQ[mi][ks][3] = *(const uint32_t*)&Qg[r1 * DHH + ks * 16 + 2 * c + 8];
        }
    }

    float o[2][8][4];
    #pragma unroll
    for (int mi = 0; mi < 2; mi++)
        #pragma unroll
        for (int t = 0; t < 8; t++)
            #pragma unroll
            for (int e = 0; e < 4; e++) o[mi][t][e] = 0.0f;
    float mv[2][2] = { {-INFINITY, -INFINITY}, {-INFINITY, -INFINITY} };
    float lv[2][2] = { {0.0f, 0.0f}, {0.0f, 0.0f} };

    const int pmax = qt;   // pairs 0..qt; pair p covers kv tiles 2p, 2p+1

    // prefetch one PAIR (2 K sub-tiles + 2 V sub-tiles = 16 cp16/thread)
    auto prefetch = [&](int p, int stage) {
        const uint32_t kst = sbase + (uint32_t)stage * ASTG_B;
        const uint32_t vst = kst + 2 * SUB_B;
        const __half* Kg = Kg0 + (size_t)(2 * p) * 64 * DHH;
        const __half* Vg = Vg0 + (size_t)(2 * p) * 64;
        #pragma unroll
        for (int i = 0; i < 8; i++) {
            const int idx = tid + i * 128;        // 0..1023
            const int r = idx >> 3, ch = idx & 7; // r 0..127 across both subs
            const int sub = r >> 6, rr = r & 63;
            const uint32_t off = (uint32_t)(sub * SUB_B + rr * (AKST * 2) + ch * 16);
            cp16(kst + off, &Kg[(size_t)(sub * 64 + rr) * DHH + ch * 8]);
            cp16(vst + off, &Vg[(size_t)rr * NN + sub * 64 + ch * 8]);
        }
        cp_commit();
    };

    prefetch(0, 0);
    const int row0g = qt * 128 + w * 32;

    const uint32_t bv_rowoff = (uint32_t)((lane & 7) + ((lane & 16) >> 1)) * (AKST * 2);
    const uint32_t bv_chbit  = (uint32_t)((lane >> 3) & 1) * 16;

    for (int p = 0; p <= pmax; p++) {
        asm volatile("cp.async.wait_group 0;\n" ::);
        __syncthreads();
        if (p + 1 <= pmax) prefetch(p + 1, (p + 1) & 1);

        const uint32_t kst = sbase + (uint32_t)(p & 1) * ASTG_B + bv_rowoff + bv_chbit;
        const uint32_t vst = kst + 2 * SUB_B;

        #pragma unroll
        for (int sub = 0; sub < 2; sub++) {
            const int j = 2 * p + sub;
            if (j * 64 > row0g + 31) continue;   // fully masked for this warp

            const uint32_t kb_u = kst + (uint32_t)sub * SUB_B;
            const uint32_t vb_u = vst + (uint32_t)sub * SUB_B;

            float s[2][8][4];
            #pragma unroll
            for (int mi = 0; mi < 2; mi++)
                #pragma unroll
                for (int t = 0; t < 8; t++)
                    #pragma unroll
                    for (int e = 0; e < 4; e++) s[mi][t][e] = 0.0f;

            #pragma unroll
            for (int ks = 0; ks < 4; ks++) {
                #pragma unroll
                for (int tp = 0; tp < 4; tp++) {
                    uint32_t r0, r1, r2, r3;
                    ldsm4(r0, r1, r2, r3,
                          kb_u + (uint32_t)(tp * 16) * (AKST * 2) + ks * 32);
                    #pragma unroll
                    for (int mi = 0; mi < 2; mi++) {
                        mma_f16(s[mi][2 * tp],     aQ[mi][ks], r0, r1);
                        mma_f16(s[mi][2 * tp + 1], aQ[mi][ks], r2, r3);
                    }
                }
            }

            if (j * 64 + 63 > row0g) {
                #pragma unroll
                for (int mi = 0; mi < 2; mi++) {
                    const int r0 = row0g + mi * 16 + g, r1 = r0 + 8;
                    #pragma unroll
                    for (int t = 0; t < 8; t++) {
                        const int col = j * 64 + t * 8 + 2 * c;
                        if (col     > r0) s[mi][t][0] = -INFINITY;
                        if (col + 1 > r0) s[mi][t][1] = -INFINITY;
                        if (col     > r1) s[mi][t][2] = -INFINITY;
                        if (col + 1 > r1) s[mi][t][3] = -INFINITY;
                    }
                }
            }

            float psum[2][2];
            #pragma unroll
            for (int mi = 0; mi < 2; mi++) {
                float mx0 = -INFINITY, mx1 = -INFINITY;
                #pragma unroll
                for (int t = 0; t < 8; t++) {
                    mx0 = fmaxf(mx0, fmaxf(s[mi][t][0], s[mi][t][1]));
                    mx1 = fmaxf(mx1, fmaxf(s[mi][t][2], s[mi][t][3]));
                }
                mx0 = fmaxf(mx0, __shfl_xor_sync(0xffffffffu, mx0, 1));
                mx0 = fmaxf(mx0, __shfl_xor_sync(0xffffffffu, mx0, 2));
                mx1 = fmaxf(mx1, __shfl_xor_sync(0xffffffffu, mx1, 1));
                mx1 = fmaxf(mx1, __shfl_xor_sync(0xffffffffu, mx1, 2));

                const float mn0 = fmaxf(mv[mi][0], mx0);
                const float mn1 = fmaxf(mv[mi][1], mx1);
                float sum0 = 0.0f, sum1 = 0.0f;
                #pragma unroll
                for (int t = 0; t < 8; t++) {
                    s[mi][t][0] = ex2f(s[mi][t][0] - mn0);
                    s[mi][t][1] = ex2f(s[mi][t][1] - mn0);
                    s[mi][t][2] = ex2f(s[mi][t][2] - mn1);
                    s[mi][t][3] = ex2f(s[mi][t][3] - mn1);
                    sum0 += s[mi][t][0] + s[mi][t][1];
                    sum1 += s[mi][t][2] + s[mi][t][3];
                }
                const float al0 = ex2f(mv[mi][0] - mn0);
                const float al1 = ex2f(mv[mi][1] - mn1);
                lv[mi][0] *= al0;
                lv[mi][1] *= al1;
                psum[mi][0] = sum0;
                psum[mi][1] = sum1;
                mv[mi][0] = mn0; mv[mi][1] = mn1;

                if (!__all_sync(0xffffffffu, (al0 == 1.0f) && (al1 == 1.0f))) {
                    #pragma unroll
                    for (int t = 0; t < 8; t++) {
                        o[mi][t][0] *= al0; o[mi][t][1] *= al0;
                        o[mi][t][2] *= al1; o[mi][t][3] *= al1;
                    }
                }
            }

            #pragma unroll
            for (int ks = 0; ks < 4; ks++) {
                uint32_t a[2][4];
                #pragma unroll
                for (int mi = 0; mi < 2; mi++) {
                    a[mi][0] = h2pack(s[mi][2 * ks][0],     s[mi][2 * ks][1]);
                    a[mi][1] = h2pack(s[mi][2 * ks][2],     s[mi][2 * ks][3]);
                    a[mi][2] = h2pack(s[mi][2 * ks + 1][0], s[mi][2 * ks + 1][1]);
                    a[mi][3] = h2pack(s[mi][2 * ks + 1][2], s[mi][2 * ks + 1][3]);
                }
                #pragma unroll
                for (int tp = 0; tp < 4; tp++) {
                    uint32_t r0, r1, r2, r3;
                    ldsm4(r0, r1, r2, r3,
                          vb_u + (uint32_t)(tp * 16) * (AKST * 2) + ks * 32);
                    #pragma unroll
                    for (int mi = 0; mi < 2; mi++) {
                        mma_f16(o[mi][2 * tp],     a[mi], r0, r1);
                        mma_f16(o[mi][2 * tp + 1], a[mi], r2, r3);
                    }
                }
            }

            #pragma unroll
            for (int mi = 0; mi < 2; mi++) {
                float sum0 = psum[mi][0], sum1 = psum[mi][1];
                sum0 += __shfl_xor_sync(0xffffffffu, sum0, 1);
                sum0 += __shfl_xor_sync(0xffffffffu, sum0, 2);
                sum1 += __shfl_xor_sync(0xffffffffu, sum1, 1);
                sum1 += __shfl_xor_sync(0xffffffffu, sum1, 2);
                lv[mi][0] += sum0;
                lv[mi][1] += sum1;
            }
        }
    }

    const int b = bh >> 4, h = bh & 15;
    __half* Og = g_ao + ((size_t)(b * NN + qt * 128)) * DD + h * DHH;
    #pragma unroll
    for (int mi = 0; mi < 2; mi++) {
        const float i0 = 1.0f / lv[mi][0], i1 = 1.0f / lv[mi][1];
        const int r0 = w * 32 + mi * 16 + g, r1 = r0 + 8;
        #pragma unroll
        for (int t = 0; t < 8; t++) {
            *(uint32_t*)&Og[(size_t)r0 * DD + t * 8 + 2 * c] =
                h2pack(o[mi][t][0] * i0, o[mi][t][1] * i0);
            *(uint32_t*)&Og[(size_t)r1 * DD + t * 8 + 2 * c] =
                h2pack(o[mi][t][2] * i1, o[mi][t][3] * i1);
        }
    }
}

// ============================================================================
// Launch
// ============================================================================
extern "C" void kernel_launch(void* const* d_in, const int* in_sizes, int n_in,
                              void* d_out, int out_size) {
    (void)in_sizes; (void)n_in; (void)out_size;
    const float* x   = (const float*)d_in[0];
    const float* g   = (const float*)d_in[1];
    const float* Wq  = (const float*)d_in[2];
    const float* Wkv = (const float*)d_in[3];
    const float* Wo  = (const float*)d_in[4];
    float* out = (float*)d_out;

    cudaFuncSetAttribute(gemm_mma<0>, cudaFuncAttributeMaxDynamicSharedMemorySize,
                         GEMM_SMEM_BYTES);
    cudaFuncSetAttribute(gemm_mma<1>, cudaFuncAttributeMaxDynamicSharedMemorySize,
                         GEMM_SMEM_BYTES);
    cudaFuncSetAttribute(attn_kernel, cudaFuncAttributeMaxDynamicSharedMemorySize,
                         ATTN_SMEM_BYTES);

    // 0) Fused prep: weight transpose+round (fp16, vectorized) + LayerNorm
    prep_kernel<<<2048, 256>>>(x, g, Wq, Wkv, Wo);

    // 1) Fused QKV projection (M=8192, N=3072)
    gemm_mma<0><<<dim3(24, 64), 128, GEMM_SMEM_BYTES>>>(nullptr);

    // 2) Causal flash attention (KV-pair stages: 1 barrier per 2 tiles)
    attn_kernel<<<dim3(BB * HH, 16), 128, ATTN_SMEM_BYTES>>>();

    // 3) Output projection (M=8192, N=1024) -> fp32 out
    gemm_mma<1><<<dim3(8, 64), 128, GEMM_SMEM_BYTES>>>(out);
}

// round 16
// speedup vs baseline: 1.0027x; 1.0027x over previous
#include <cuda_runtime.h>
#include <cuda_fp16.h>
#include <cstdint>

#define BB 4
#define NN 2048
#define DD 1024
#define HH 16
#define DHH 64
#define MROWS (BB * NN)   // 8192

// ---------------- scratch (device globals; no runtime allocation) ----------
__device__ __half g_xn[(size_t)MROWS * DD];   // fp16 LN output
__device__ __half g_q [(size_t)MROWS * DD];   // [b,h,n,dh], pre-scaled by 0.125*lg2e
__device__ __half g_k [(size_t)MROWS * DD];   // [b,h,n,dh]
__device__ __half g_v [(size_t)MROWS * DD];   // [b,h,dh,n]  (TRANSPOSED)
__device__ __half g_ao[(size_t)MROWS * DD];   // [b,n,(h dh)]
__device__ __half g_wt [(size_t)3072 * DD];   // [Wq|Wkv]^T rows n, fp16 (Wq part scaled)
__device__ __half g_wot[(size_t)DD * DD];     // Wo^T, fp16

#define QSCALE 0.18033688f   // 0.125 * log2(e)

// ---------------- PTX helpers ----------------------------------------------
__device__ __forceinline__ float ex2f(float x) {
    float y;
    asm("ex2.approx.ftz.f32 %0, %1;" : "=f"(y) : "f"(x));
    return y;
}
__device__ __forceinline__ uint32_t h2pack(float lo, float hi) {
    __half2 h = __floats2half2_rn(lo, hi);
    return *(uint32_t*)&h;
}
__device__ __forceinline__ void mma_f16(float* d, const uint32_t* a,
                                        uint32_t b0, uint32_t b1) {
    asm volatile(
        "mma.sync.aligned.m16n8k16.row.col.f32.f16.f16.f32 "
        "{%0,%1,%2,%3},{%4,%5,%6,%7},{%8,%9},{%0,%1,%2,%3};\n"
        : "+f"(d[0]), "+f"(d[1]), "+f"(d[2]), "+f"(d[3])
        : "r"(a[0]), "r"(a[1]), "r"(a[2]), "r"(a[3]), "r"(b0), "r"(b1));
}
__device__ __forceinline__ void ldsm4(uint32_t& r0, uint32_t& r1, uint32_t& r2,
                                      uint32_t& r3, uint32_t addr) {
    asm volatile("ldmatrix.sync.aligned.m8n8.x4.shared.b16 {%0,%1,%2,%3}, [%4];"
                 : "=r"(r0), "=r"(r1), "=r"(r2), "=r"(r3) : "r"(addr));
}
__device__ __forceinline__ void cp16(uint32_t dst, const void* src) {
    asm volatile("cp.async.cg.shared.global [%0], [%1], 16;\n" :: "r"(dst), "l"(src));
}
__device__ __forceinline__ void cp_commit() {
    asm volatile("cp.async.commit_group;\n" ::);
}

// ============================================================================
// Fused prep v2: blocks 0..1023 transpose 64x64 weight tiles (vectorized);
// blocks 1024..2047 LayerNorm (warp per row).
// ============================================================================
__global__ __launch_bounds__(256) void prep_kernel(const float* __restrict__ x,
                                                   const float* __restrict__ gamma,
                                                   const float* __restrict__ wq,
                                                   const float* __restrict__ wkv,
                                                   const float* __restrict__ wo) {
    const int bid = blockIdx.x;
    if (bid < 1024) {
        __shared__ float ts[64][65];
        const float* S; __half* D; int Nn, rowbase, ti; float scale;
        if (bid < 256)      { S = wq;  D = g_wt;  Nn = 1024; rowbase = 0;    ti = bid;       scale = QSCALE; }
        else if (bid < 768) { S = wkv; D = g_wt;  Nn = 2048; rowbase = 1024; ti = bid - 256; scale = 1.0f; }
        else                { S = wo;  D = g_wot; Nn = 1024; rowbase = 0;    ti = bid - 768; scale = 1.0f; }
        const int nt = Nn / 64;
        const int k0 = (ti / nt) * 64, n0 = (ti % nt) * 64;
        const int tid = threadIdx.x;
        {
            const int rl = tid >> 4, c4 = (tid & 15) << 2;
            #pragma unroll
            for (int i = 0; i < 4; i++) {
                const int row = rl + i * 16;
                float4 v = *(const float4*)&S[(size_t)(k0 + row) * Nn + n0 + c4];
                ts[row][c4 + 0] = v.x * scale;
                ts[row][c4 + 1] = v.y * scale;
                ts[row][c4 + 2] = v.z * scale;
                ts[row][c4 + 3] = v.w * scale;
            }
        }
        __syncthreads();
        {
            const int nr = tid >> 2, kc = (tid & 3) * 16;
            uint32_t p[8];
            #pragma unroll
            for (int j = 0; j < 8; j++)
                p[j] = h2pack(ts[kc + 2 * j][nr], ts[kc + 2 * j + 1][nr]);
            __half* dst = D + (size_t)(rowbase + n0 + nr) * DD + k0 + kc;
            *(uint4*)dst       = make_uint4(p[0], p[1], p[2], p[3]);
            *(uint4*)(dst + 8) = make_uint4(p[4], p[5], p[6], p[7]);
        }
    } else {
        const int wid = threadIdx.x >> 5, lane = threadIdx.x & 31;
        const int row = (bid - 1024) * 8 + wid;
        const float4* xr = (const float4*)(x + (size_t)row * DD);
        const float4* gr = (const float4*)gamma;
        float4 v[8];
        float s = 0.f, ss = 0.f;
        #pragma unroll
        for (int j = 0; j < 8; j++) {
            v[j] = xr[lane + j * 32];
            s  += v[j].x + v[j].y + v[j].z + v[j].w;
            ss += v[j].x*v[j].x + v[j].y*v[j].y + v[j].z*v[j].z + v[j].w*v[j].w;
        }
        #pragma unroll
        for (int off = 16; off > 0; off >>= 1) {
            s  += __shfl_xor_sync(0xffffffffu, s,  off);
            ss += __shfl_xor_sync(0xffffffffu, ss, off);
        }
        const float mu = s * (1.0f / DD);
        const float rstd = rsqrtf(ss * (1.0f / DD) - mu * mu + 1e-5f);
        uint2* orow = (uint2*)(g_xn + (size_t)row * DD);
        #pragma unroll
        for (int j = 0; j < 8; j++) {
            float4 gv = gr[lane + j * 32];
            uint2 o;
            o.x = h2pack((v[j].x - mu) * rstd * gv.x, (v[j].y - mu) * rstd * gv.y);
            o.y = h2pack((v[j].z - mu) * rstd * gv.z, (v[j].w - mu) * rstd * gv.w);
            orow[lane + j * 32] = o;
        }
    }
}

// ============================================================================
// fp16 m16n8k16 GEMM: CTA 128x128, 4 warps, warp 64x64 (0.25 ldsm/MMA),
// 3-stage cp.async, one barrier per k-chunk.
// ============================================================================
#define GT_BYTES 16384
#define GSTAGE_BYTES (2 * GT_BYTES)
#define GEMM_SMEM_BYTES (3 * GSTAGE_BYTES)

template<int MODE>
__global__ __launch_bounds__(128, 2) void gemm_mma(float* __restrict__ C) {
    extern __shared__ char smc[];
    const uint32_t sb = (uint32_t)__cvta_generic_to_shared(smc);

    const __half* A  = (MODE == 0) ? g_xn : g_ao;
    const __half* Bt = (MODE == 0) ? g_wt : g_wot;

    const int m0 = blockIdx.y * 128;
    const int c0 = blockIdx.x * 128;

    const int tid = threadIdx.x;
    const int wid = tid >> 5, lane = tid & 31;
    const int wm = wid & 1;
    const int wn = wid >> 1;

    float acc[4][8][4];
    #pragma unroll
    for (int i = 0; i < 4; i++)
        #pragma unroll
        for (int t = 0; t < 8; t++)
            #pragma unroll
            for (int e = 0; e < 4; e++) acc[i][t][e] = 0.0f;

    const int lrow = tid >> 3, lch = tid & 7;

    auto load_tile = [&](int j, int stage) {
        const int k0 = j * 64;
        const uint32_t ab = sb + (uint32_t)stage * GSTAGE_BYTES;
        const uint32_t bb = ab + GT_BYTES;
        #pragma unroll
        for (int i = 0; i < 8; i++) {
            const int row = lrow + i * 16;
            const uint32_t off = (uint32_t)(row * 128 + (((lch ^ (row & 7)) & 7) << 4));
            cp16(ab + off, &A [(size_t)(m0 + row) * DD + k0 + lch * 8]);
            cp16(bb + off, &Bt[(size_t)(c0 + row) * DD + k0 + lch * 8]);
        }
        cp_commit();
    };

    uint32_t a_rowb[4];
    #pragma unroll
    for (int ig = 0; ig < 4; ig++)
        a_rowb[ig] = (uint32_t)(wm * 64 + ig * 16 + (lane & 15)) * 128;
    const int a_chbit = lane >> 4;
    uint32_t b_rowb[4];
    #pragma unroll
    for (int grp = 0; grp < 4; grp++)
        b_rowb[grp] = (uint32_t)(wn * 64 + grp * 16 + (lane & 7) + ((lane & 16) >> 1)) * 128;
    const int b_chbit = (lane >> 3) & 1;
    const int lxor = lane & 7;

    load_tile(0, 0);
    load_tile(1, 1);

    int cb = 0, nb = 2;
    for (int j = 0; j < 16; j++) {
        if (j < 15) asm volatile("cp.async.wait_group 1;\n" ::);
        else        asm volatile("cp.async.wait_group 0;\n" ::);
        __syncthreads();
        if (j + 2 < 16) {
            load_tile(j + 2, nb);
            nb = (nb == 2) ? 0 : nb + 1;
        }

        const uint32_t ab = sb + (uint32_t)cb * GSTAGE_BYTES;
        const uint32_t bb = ab + GT_BYTES;
        #pragma unroll
        for (int ks = 0; ks < 4; ks++) {
            uint32_t af[4][4];
            const uint32_t axo = (uint32_t)(((2 * ks + a_chbit) ^ lxor) << 4);
            #pragma unroll
            for (int ig = 0; ig < 4; ig++)
                ldsm4(af[ig][0], af[ig][1], af[ig][2], af[ig][3],
                      ab + a_rowb[ig] + axo);
            uint32_t bf[4][4];
            const uint32_t bxo = (uint32_t)(((2 * ks + b_chbit) ^ lxor) << 4);
            #pragma unroll
            for (int grp = 0; grp < 4; grp++)
                ldsm4(bf[grp][0], bf[grp][1], bf[grp][2], bf[grp][3],
                      bb + b_rowb[grp] + bxo);
            #pragma unroll
            for (int ig = 0; ig < 4; ig++)
                #pragma unroll
                for (int t = 0; t < 8; t++)
                    mma_f16(acc[ig][t], af[ig],
                            bf[t >> 1][(t & 1) * 2], bf[t >> 1][(t & 1) * 2 + 1]);
        }
        cb = (cb == 2) ? 0 : cb + 1;
    }

    const int g = lane >> 2, cq = lane & 3;
    #pragma unroll
    for (int ig = 0; ig < 4; ig++) {
        #pragma unroll
        for (int t = 0; t < 8; t++) {
            const int row = m0 + wm * 64 + ig * 16 + g;
            const int col = c0 + wn * 64 + t * 8 + 2 * cq;
            float* d = acc[ig][t];
            if (MODE == 1) {
                *(float2*)&C[(size_t)row * DD + col]       = make_float2(d[0], d[1]);
                *(float2*)&C[(size_t)(row + 8) * DD + col] = make_float2(d[2], d[3]);
            } else {
                const int b = row >> 11, n = row & 2047;
                if (col < 2048) {
                    __half* dst = (col < 1024) ? g_q : g_k;
                    const int cc = col & 1023;
                    const int h = cc >> 6, dh = cc & 63;
                    __half* base = dst + (((size_t)(b * HH + h) * NN) * DHH + dh);
                    *(uint32_t*)&base[(size_t)n * DHH]       = h2pack(d[0], d[1]);
                    *(uint32_t*)&base[(size_t)(n + 8) * DHH] = h2pack(d[2], d[3]);
                } else {
                    const int cc = col - 2048;
                    const int h = cc >> 6, dh = cc & 63;
                    __half* base = g_v + ((size_t)(b * HH + h) * DHH + dh) * NN;
                    base[n]          = __float2half_rn(d[0]);
                    base[NN + n]     = __float2half_rn(d[1]);
                    base[n + 8]      = __float2half_rn(d[2]);
                    base[NN + n + 8] = __float2half_rn(d[3]);
                }
            }
        }
    }
}

// ============================================================================
// Causal flash attention fp16 (best measured config): 4 warps x 32 q-rows,
// 128 threads, 2 CTAs/SM, m16n8k16, base-2 softmax (scale folded into Wq),
// deferred l-reduction, warp-uniform rescale skip, 3-stage pipeline,
// one barrier per tile, heavy-first grid.
// ============================================================================
#define AKST 72
#define KSTG_B (64 * AKST * 2)          // one K (or V) stage = 9216 B
#define ATTN_SMEM_BYTES (6 * KSTG_B)    // 3 stages x (K + V) = 55296

__global__ __launch_bounds__(128, 2) void attn_kernel() {
    extern __shared__ char smc[];
    const uint32_t sbase = (uint32_t)__cvta_generic_to_shared(smc);
    const uint32_t ks_u = sbase;
    const uint32_t vs_u = sbase + 3 * KSTG_B;

    const int bh = blockIdx.x;                              // 0..63
    const int qt = (int)gridDim.y - 1 - (int)blockIdx.y;    // heavy first
    const int tid = threadIdx.x;
    const int w = tid >> 5;
    const int lane = tid & 31;
    const int g = lane >> 2;
    const int c = lane & 3;

    const size_t hoff = (size_t)bh * NN * DHH;
    const __half* Qg  = g_q + hoff + (size_t)qt * 128 * DHH;
    const __half* Kg0 = g_k + hoff;
    const __half* Vg0 = g_v + hoff;   // [dh][n]

    uint32_t aQ[2][4][4];
    #pragma unroll
    for (int mi = 0; mi < 2; mi++) {
        const int r0 = w * 32 + mi * 16 + g, r1 = r0 + 8;
        #pragma unroll
        for (int ks = 0; ks < 4; ks++) {
            aQ[mi][ks][0] = *(const uint32_t*)&Qg[r0 * DHH + ks * 16 + 2 * c];
            aQ[mi][ks][1] = *(const uint32_t*)&Qg[r1 * DHH + ks * 16 + 2 * c];
            aQ[mi][ks][2] = *(const uint32_t*)&Qg[r0 * DHH + ks * 16 + 2 * c + 8];
            aQ[mi][ks][3] = *(const uint32_t*)&Qg[r1 * DHH + ks * 16 + 2 * c + 8];
        }
    }

    float o[2][8][4];
    #pragma unroll
    for (int mi = 0; mi < 2; mi++)
        #pragma unroll
        for (int t = 0; t < 8; t++)
            #pragma unroll
            for (int e = 0; e < 4; e++) o[mi][t][e] = 0.0f;
    float mv[2][2] = { {-INFINITY, -INFINITY}, {-INFINITY, -INFINITY} };
    float lv[2][2] = { {0.0f, 0.0f}, {0.0f, 0.0f} };

    const int jmax = 2 * qt + 1;

    auto prefetch = [&](int j, int stage) {
        const __half* Kg = Kg0 + (size_t)j * 64 * DHH;
        const __half* Vg = Vg0 + (size_t)j * 64;
        #pragma unroll
        for (int i = 0; i < 4; i++) {
            const int idx = tid + i * 128;        // 0..511
            const int r = idx >> 3, ch = idx & 7;
            const uint32_t off = (uint32_t)((stage * 64 + r) * (AKST * 2) + ch * 16);
            cp16(ks_u + off, &Kg[r * DHH + ch * 8]);
            cp16(vs_u + off, &Vg[(size_t)r * NN + ch * 8]);
        }
        cp_commit();
    };

    prefetch(0, 0);
    prefetch(1, 1);   // jmax >= 1 always
    const int row0g = qt * 128 + w * 32;

    const uint32_t bv_rowoff = (uint32_t)((lane & 7) + ((lane & 16) >> 1)) * (AKST * 2);
    const uint32_t bv_chbit  = (uint32_t)((lane >> 3) & 1) * 16;

    int cbuf = 0, nbuf = 2;
    for (int j = 0; j <= jmax; j++) {
        if (j < jmax) asm volatile("cp.async.wait_group 1;\n" ::);
        else          asm volatile("cp.async.wait_group 0;\n" ::);
        __syncthreads();
        if (j + 2 <= jmax) {
            prefetch(j + 2, nbuf);
            nbuf = (nbuf == 2) ? 0 : nbuf + 1;
        }

        const bool skip = (j * 64 > row0g + 31);
        if (!skip) {
            const uint32_t kb_u = ks_u + (uint32_t)(cbuf * KSTG_B) + bv_rowoff + bv_chbit;
            const uint32_t vb_u = vs_u + (uint32_t)(cbuf * KSTG_B) + bv_rowoff + bv_chbit;

            float s[2][8][4];
            #pragma unroll
            for (int mi = 0; mi < 2; mi++)
                #pragma unroll
                for (int t = 0; t < 8; t++)
                    #pragma unroll
                    for (int e = 0; e < 4; e++) s[mi][t][e] = 0.0f;

            #pragma unroll
            for (int ks = 0; ks < 4; ks++) {
                #pragma unroll
                for (int tp = 0; tp < 4; tp++) {
                    uint32_t r0, r1, r2, r3;
                    ldsm4(r0, r1, r2, r3,
                          kb_u + (uint32_t)(tp * 16) * (AKST * 2) + ks * 32);
                    #pragma unroll
                    for (int mi = 0; mi < 2; mi++) {
                        mma_f16(s[mi][2 * tp],     aQ[mi][ks], r0, r1);
                        mma_f16(s[mi][2 * tp + 1], aQ[mi][ks], r2, r3);
                    }
                }
            }

            if (j * 64 + 63 > row0g) {
                #pragma unroll
                for (int mi = 0; mi < 2; mi++) {
                    const int r0 = row0g + mi * 16 + g, r1 = r0 + 8;
                    #pragma unroll
                    for (int t = 0; t < 8; t++) {
                        const int col = j * 64 + t * 8 + 2 * c;
                        if (col     > r0) s[mi][t][0] = -INFINITY;
                        if (col + 1 > r0) s[mi][t][1] = -INFINITY;
                        if (col     > r1) s[mi][t][2] = -INFINITY;
                        if (col + 1 > r1) s[mi][t][3] = -INFINITY;
                    }
                }
            }

            float psum[2][2];
            #pragma unroll
            for (int mi = 0; mi < 2; mi++) {
                float mx0 = -INFINITY, mx1 = -INFINITY;
                #pragma unroll
                for (int t = 0; t < 8; t++) {
                    mx0 = fmaxf(mx0, fmaxf(s[mi][t][0], s[mi][t][1]));
                    mx1 = fmaxf(mx1, fmaxf(s[mi][t][2], s[mi][t][3]));
                }
                mx0 = fmaxf(mx0, __shfl_xor_sync(0xffffffffu, mx0, 1));
                mx0 = fmaxf(mx0, __shfl_xor_sync(0xffffffffu, mx0, 2));
                mx1 = fmaxf(mx1, __shfl_xor_sync(0xffffffffu, mx1, 1));
                mx1 = fmaxf(mx1, __shfl_xor_sync(0xffffffffu, mx1, 2));

                const float mn0 = fmaxf(mv[mi][0], mx0);
                const float mn1 = fmaxf(mv[mi][1], mx1);
                float sum0 = 0.0f, sum1 = 0.0f;
                #pragma unroll
                for (int t = 0; t < 8; t++) {
                    s[mi][t][0] = ex2f(s[mi][t][0] - mn0);
                    s[mi][t][1] = ex2f(s[mi][t][1] - mn0);
                    s[mi][t][2] = ex2f(s[mi][t][2] - mn1);
                    s[mi][t][3] = ex2f(s[mi][t][3] - mn1);
                    sum0 += s[mi][t][0] + s[mi][t][1];
                    sum1 += s[mi][t][2] + s[mi][t][3];
                }
                const float al0 = ex2f(mv[mi][0] - mn0);
                const float al1 = ex2f(mv[mi][1] - mn1);
                lv[mi][0] *= al0;
                lv[mi][1] *= al1;
                psum[mi][0] = sum0;
                psum[mi][1] = sum1;
                mv[mi][0] = mn0; mv[mi][1] = mn1;

                if (!__all_sync(0xffffffffu, (al0 == 1.0f) && (al1 == 1.0f))) {
                    #pragma unroll
                    for (int t = 0; t < 8; t++) {
                        o[mi][t][0] *= al0; o[mi][t][1] *= al0;
                        o[mi][t][2] *= al1; o[mi][t][3] *= al1;
                    }
                }
            }

            #pragma unroll
            for (int ks = 0; ks < 4; ks++) {
                uint32_t a[2][4];
                #pragma unroll
                for (int mi = 0; mi < 2; mi++) {
                    a[mi][0] = h2pack(s[mi][2 * ks][0],     s[mi][2 * ks][1]);
                    a[mi][1] = h2pack(s[mi][2 * ks][2],     s[mi][2 * ks][3]);
                    a[mi][2] = h2pack(s[mi][2 * ks + 1][0], s[mi][2 * ks + 1][1]);
                    a[mi][3] = h2pack(s[mi][2 * ks + 1][2], s[mi][2 * ks + 1][3]);
                }
                #pragma unroll
                for (int tp = 0; tp < 4; tp++) {
                    uint32_t r0, r1, r2, r3;
                    ldsm4(r0, r1, r2, r3,
                          vb_u + (uint32_t)(tp * 16) * (AKST * 2) + ks * 32);
                    #pragma unroll
                    for (int mi = 0; mi < 2; mi++) {
                        mma_f16(o[mi][2 * tp],     a[mi], r0, r1);
                        mma_f16(o[mi][2 * tp + 1], a[mi], r2, r3);
                    }
                }
            }

            #pragma unroll
            for (int mi = 0; mi < 2; mi++) {
                float sum0 = psum[mi][0], sum1 = psum[mi][1];
                sum0 += __shfl_xor_sync(0xffffffffu, sum0, 1);
                sum0 += __shfl_xor_sync(0xffffffffu, sum0, 2);
                sum1 += __shfl_xor_sync(0xffffffffu, sum1, 1);
                sum1 += __shfl_xor_sync(0xffffffffu, sum1, 2);
                lv[mi][0] += sum0;
                lv[mi][1] += sum1;
            }
        }
        cbuf = (cbuf == 2) ? 0 : cbuf + 1;
    }

    const int b = bh >> 4, h = bh & 15;
    __half* Og = g_ao + ((size_t)(b * NN + qt * 128)) * DD + h * DHH;
    #pragma unroll
    for (int mi = 0; mi < 2; mi++) {
        const float i0 = 1.0f / lv[mi][0], i1 = 1.0f / lv[mi][1];
        const int r0 = w * 32 + mi * 16 + g, r1 = r0 + 8;
        #pragma unroll
        for (int t = 0; t < 8; t++) {
            *(uint32_t*)&Og[(size_t)r0 * DD + t * 8 + 2 * c] =
                h2pack(o[mi][t][0] * i0, o[mi][t][1] * i0);
            *(uint32_t*)&Og[(size_t)r1 * DD + t * 8 + 2 * c] =
                h2pack(o[mi][t][2] * i1, o[mi][t][3] * i1);
        }
    }
}

// ============================================================================
// Launch
// ============================================================================
extern "C" void kernel_launch(void* const* d_in, const int* in_sizes, int n_in,
                              void* d_out, int out_size) {
    (void)in_sizes; (void)n_in; (void)out_size;
    const float* x   = (const float*)d_in[0];
    const float* g   = (const float*)d_in[1];
    const float* Wq  = (const float*)d_in[2];
    const float* Wkv = (const float*)d_in[3];
    const float* Wo  = (const float*)d_in[4];
    float* out = (float*)d_out;

    cudaFuncSetAttribute(gemm_mma<0>, cudaFuncAttributeMaxDynamicSharedMemorySize,
                         GEMM_SMEM_BYTES);
    cudaFuncSetAttribute(gemm_mma<1>, cudaFuncAttributeMaxDynamicSharedMemorySize,
                         GEMM_SMEM_BYTES);
    cudaFuncSetAttribute(attn_kernel, cudaFuncAttributeMaxDynamicSharedMemorySize,
                         ATTN_SMEM_BYTES);

    // 0) Fused prep: weight transpose+round (fp16, vectorized) + LayerNorm
    prep_kernel<<<2048, 256>>>(x, g, Wq, Wkv, Wo);

    // 1) Fused QKV projection (M=8192, N=3072)
    gemm_mma<0><<<dim3(24, 64), 128, GEMM_SMEM_BYTES>>>(nullptr);

    // 2) Causal flash attention (128-q-row CTAs, 128 threads, 2 CTAs/SM)
    attn_kernel<<<dim3(BB * HH, 16), 128, ATTN_SMEM_BYTES>>>();

    // 3) Output projection (M=8192, N=1024) -> fp32 out
    gemm_mma<1><<<dim3(8, 64), 128, GEMM_SMEM_BYTES>>>(out);
}

// round 17
// speedup vs baseline: 1.0069x; 1.0042x over previous
#include <cuda_runtime.h>
#include <cuda_fp16.h>
#include <cstdint>

#define BB 4
#define NN 2048
#define DD 1024
#define HH 16
#define DHH 64
#define MROWS (BB * NN)   // 8192

// ---------------- scratch (device globals; no runtime allocation) ----------
__device__ __half g_xn[(size_t)MROWS * DD];   // fp16 LN output
__device__ __half g_q [(size_t)MROWS * DD];   // [b,h,n,dh], pre-scaled by 0.125*lg2e
__device__ __half g_k [(size_t)MROWS * DD];   // [b,h,n,dh]
__device__ __half g_v [(size_t)MROWS * DD];   // [b,h,dh,n]  (TRANSPOSED)
__device__ __half g_ao[(size_t)MROWS * DD];   // [b,n,(h dh)]
__device__ __half g_wt [(size_t)3072 * DD];   // [Wq|Wkv]^T rows n, fp16 (Wq part scaled)
__device__ __half g_wot[(size_t)DD * DD];     // Wo^T, fp16

#define QSCALE 0.18033688f   // 0.125 * log2(e)

// ---------------- PTX helpers ----------------------------------------------
__device__ __forceinline__ float ex2f(float x) {
    float y;
    asm("ex2.approx.ftz.f32 %0, %1;" : "=f"(y) : "f"(x));
    return y;
}
__device__ __forceinline__ uint32_t h2pack(float lo, float hi) {
    __half2 h = __floats2half2_rn(lo, hi);
    return *(uint32_t*)&h;
}
__device__ __forceinline__ void mma_f16(float* d, const uint32_t* a,
                                        uint32_t b0, uint32_t b1) {
    asm volatile(
        "mma.sync.aligned.m16n8k16.row.col.f32.f16.f16.f32 "
        "{%0,%1,%2,%3},{%4,%5,%6,%7},{%8,%9},{%0,%1,%2,%3};\n"
        : "+f"(d[0]), "+f"(d[1]), "+f"(d[2]), "+f"(d[3])
        : "r"(a[0]), "r"(a[1]), "r"(a[2]), "r"(a[3]), "r"(b0), "r"(b1));
}
__device__ __forceinline__ void ldsm4(uint32_t& r0, uint32_t& r1, uint32_t& r2,
                                      uint32_t& r3, uint32_t addr) {
    asm volatile("ldmatrix.sync.aligned.m8n8.x4.shared.b16 {%0,%1,%2,%3}, [%4];"
                 : "=r"(r0), "=r"(r1), "=r"(r2), "=r"(r3) : "r"(addr));
}
__device__ __forceinline__ void cp16(uint32_t dst, const void* src) {
    asm volatile("cp.async.cg.shared.global [%0], [%1], 16;\n" :: "r"(dst), "l"(src));
}
__device__ __forceinline__ void cp_commit() {
    asm volatile("cp.async.commit_group;\n" ::);
}

// ============================================================================
// Fused prep v2: blocks 0..1023 transpose 64x64 weight tiles (vectorized);
// blocks 1024..2047 LayerNorm (warp per row).
// ============================================================================
__global__ __launch_bounds__(256) void prep_kernel(const float* __restrict__ x,
                                                   const float* __restrict__ gamma,
                                                   const float* __restrict__ wq,
                                                   const float* __restrict__ wkv,
                                                   const float* __restrict__ wo) {
    const int bid = blockIdx.x;
    if (bid < 1024) {
        __shared__ float ts[64][65];
        const float* S; __half* D; int Nn, rowbase, ti; float scale;
        if (bid < 256)      { S = wq;  D = g_wt;  Nn = 1024; rowbase = 0;    ti = bid;       scale = QSCALE; }
        else if (bid < 768) { S = wkv; D = g_wt;  Nn = 2048; rowbase = 1024; ti = bid - 256; scale = 1.0f; }
        else                { S = wo;  D = g_wot; Nn = 1024; rowbase = 0;    ti = bid - 768; scale = 1.0f; }
        const int nt = Nn / 64;
        const int k0 = (ti / nt) * 64, n0 = (ti % nt) * 64;
        const int tid = threadIdx.x;
        {
            const int rl = tid >> 4, c4 = (tid & 15) << 2;
            #pragma unroll
            for (int i = 0; i < 4; i++) {
                const int row = rl + i * 16;
                float4 v = *(const float4*)&S[(size_t)(k0 + row) * Nn + n0 + c4];
                ts[row][c4 + 0] = v.x * scale;
                ts[row][c4 + 1] = v.y * scale;
                ts[row][c4 + 2] = v.z * scale;
                ts[row][c4 + 3] = v.w * scale;
            }
        }
        __syncthreads();
        {
            const int nr = tid >> 2, kc = (tid & 3) * 16;
            uint32_t p[8];
            #pragma unroll
            for (int j = 0; j < 8; j++)
                p[j] = h2pack(ts[kc + 2 * j][nr], ts[kc + 2 * j + 1][nr]);
            __half* dst = D + (size_t)(rowbase + n0 + nr) * DD + k0 + kc;
            *(uint4*)dst       = make_uint4(p[0], p[1], p[2], p[3]);
            *(uint4*)(dst + 8) = make_uint4(p[4], p[5], p[6], p[7]);
        }
    } else {
        const int wid = threadIdx.x >> 5, lane = threadIdx.x & 31;
        const int row = (bid - 1024) * 8 + wid;
        const float4* xr = (const float4*)(x + (size_t)row * DD);
        const float4* gr = (const float4*)gamma;
        float4 v[8];
        float s = 0.f, ss = 0.f;
        #pragma unroll
        for (int j = 0; j < 8; j++) {
            v[j] = xr[lane + j * 32];
            s  += v[j].x + v[j].y + v[j].z + v[j].w;
            ss += v[j].x*v[j].x + v[j].y*v[j].y + v[j].z*v[j].z + v[j].w*v[j].w;
        }
        #pragma unroll
        for (int off = 16; off > 0; off >>= 1) {
            s  += __shfl_xor_sync(0xffffffffu, s,  off);
            ss += __shfl_xor_sync(0xffffffffu, ss, off);
        }
        const float mu = s * (1.0f / DD);
        const float rstd = rsqrtf(ss * (1.0f / DD) - mu * mu + 1e-5f);
        uint2* orow = (uint2*)(g_xn + (size_t)row * DD);
        #pragma unroll
        for (int j = 0; j < 8; j++) {
            float4 gv = gr[lane + j * 32];
            uint2 o;
            o.x = h2pack((v[j].x - mu) * rstd * gv.x, (v[j].y - mu) * rstd * gv.y);
            o.y = h2pack((v[j].z - mu) * rstd * gv.z, (v[j].w - mu) * rstd * gv.w);
            orow[lane + j * 32] = o;
        }
    }
}

// ============================================================================
// fp16 m16n8k16 GEMM: CTA 128x128, 4 warps, warp 64x64 (0.25 ldsm/MMA),
// 3-stage cp.async, one barrier per k-chunk.
// ============================================================================
#define GT_BYTES 16384
#define GSTAGE_BYTES (2 * GT_BYTES)
#define GEMM_SMEM_BYTES (3 * GSTAGE_BYTES)

template<int MODE>
__global__ __launch_bounds__(128, 2) void gemm_mma(float* __restrict__ C) {
    extern __shared__ char smc[];
    const uint32_t sb = (uint32_t)__cvta_generic_to_shared(smc);

    const __half* A  = (MODE == 0) ? g_xn : g_ao;
    const __half* Bt = (MODE == 0) ? g_wt : g_wot;

    const int m0 = blockIdx.y * 128;
    const int c0 = blockIdx.x * 128;

    const int tid = threadIdx.x;
    const int wid = tid >> 5, lane = tid & 31;
    const int wm = wid & 1;
    const int wn = wid >> 1;

    float acc[4][8][4];
    #pragma unroll
    for (int i = 0; i < 4; i++)
        #pragma unroll
        for (int t = 0; t < 8; t++)
            #pragma unroll
            for (int e = 0; e < 4; e++) acc[i][t][e] = 0.0f;

    const int lrow = tid >> 3, lch = tid & 7;

    auto load_tile = [&](int j, int stage) {
        const int k0 = j * 64;
        const uint32_t ab = sb + (uint32_t)stage * GSTAGE_BYTES;
        const uint32_t bb = ab + GT_BYTES;
        #pragma unroll
        for (int i = 0; i < 8; i++) {
            const int row = lrow + i * 16;
            const uint32_t off = (uint32_t)(row * 128 + (((lch ^ (row & 7)) & 7) << 4));
            cp16(ab + off, &A [(size_t)(m0 + row) * DD + k0 + lch * 8]);
            cp16(bb + off, &Bt[(size_t)(c0 + row) * DD + k0 + lch * 8]);
        }
        cp_commit();
    };

    uint32_t a_rowb[4];
    #pragma unroll
    for (int ig = 0; ig < 4; ig++)
        a_rowb[ig] = (uint32_t)(wm * 64 + ig * 16 + (lane & 15)) * 128;
    const int a_chbit = lane >> 4;
    uint32_t b_rowb[4];
    #pragma unroll
    for (int grp = 0; grp < 4; grp++)
        b_rowb[grp] = (uint32_t)(wn * 64 + grp * 16 + (lane & 7) + ((lane & 16) >> 1)) * 128;
    const int b_chbit = (lane >> 3) & 1;
    const int lxor = lane & 7;

    load_tile(0, 0);
    load_tile(1, 1);

    int cb = 0, nb = 2;
    for (int j = 0; j < 16; j++) {
        if (j < 15) asm volatile("cp.async.wait_group 1;\n" ::);
        else        asm volatile("cp.async.wait_group 0;\n" ::);
        __syncthreads();
        if (j + 2 < 16) {
            load_tile(j + 2, nb);
            nb = (nb == 2) ? 0 : nb + 1;
        }

        const uint32_t ab = sb + (uint32_t)cb * GSTAGE_BYTES;
        const uint32_t bb = ab + GT_BYTES;
        #pragma unroll
        for (int ks = 0; ks < 4; ks++) {
            uint32_t af[4][4];
            const uint32_t axo = (uint32_t)(((2 * ks + a_chbit) ^ lxor) << 4);
            #pragma unroll
            for (int ig = 0; ig < 4; ig++)
                ldsm4(af[ig][0], af[ig][1], af[ig][2], af[ig][3],
                      ab + a_rowb[ig] + axo);
            uint32_t bf[4][4];
            const uint32_t bxo = (uint32_t)(((2 * ks + b_chbit) ^ lxor) << 4);
            #pragma unroll
            for (int grp = 0; grp < 4; grp++)
                ldsm4(bf[grp][0], bf[grp][1], bf[grp][2], bf[grp][3],
                      bb + b_rowb[grp] + bxo);
            #pragma unroll
            for (int ig = 0; ig < 4; ig++)
                #pragma unroll
                for (int t = 0; t < 8; t++)
                    mma_f16(acc[ig][t], af[ig],
                            bf[t >> 1][(t & 1) * 2], bf[t >> 1][(t & 1) * 2 + 1]);
        }
        cb = (cb == 2) ? 0 : cb + 1;
    }

    const int g = lane >> 2, cq = lane & 3;
    #pragma unroll
    for (int ig = 0; ig < 4; ig++) {
        #pragma unroll
        for (int t = 0; t < 8; t++) {
            const int row = m0 + wm * 64 + ig * 16 + g;
            const int col = c0 + wn * 64 + t * 8 + 2 * cq;
            float* d = acc[ig][t];
            if (MODE == 1) {
                *(float2*)&C[(size_t)row * DD + col]       = make_float2(d[0], d[1]);
                *(float2*)&C[(size_t)(row + 8) * DD + col] = make_float2(d[2], d[3]);
            } else {
                const int b = row >> 11, n = row & 2047;
                if (col < 2048) {
                    __half* dst = (col < 1024) ? g_q : g_k;
                    const int cc = col & 1023;
                    const int h = cc >> 6, dh = cc & 63;
                    __half* base = dst + (((size_t)(b * HH + h) * NN) * DHH + dh);
                    *(uint32_t*)&base[(size_t)n * DHH]       = h2pack(d[0], d[1]);
                    *(uint32_t*)&base[(size_t)(n + 8) * DHH] = h2pack(d[2], d[3]);
                } else {
                    const int cc = col - 2048;
                    const int h = cc >> 6, dh = cc & 63;
                    __half* base = g_v + ((size_t)(b * HH + h) * DHH + dh) * NN;
                    base[n]          = __float2half_rn(d[0]);
                    base[NN + n]     = __float2half_rn(d[1]);
                    base[n + 8]      = __float2half_rn(d[2]);
                    base[NN + n + 8] = __float2half_rn(d[3]);
                }
            }
        }
    }
}

// ============================================================================
// Causal flash attention fp16 (best measured config + startup overlap):
// 4 warps x 32 q-rows, 128 threads, 2 CTAs/SM, m16n8k16, base-2 softmax
// (scale folded into Wq), deferred l-reduction, warp-uniform rescale skip,
// 3-stage pipeline with initial prefetch issued BEFORE Q fragment loads.
// ============================================================================
#define AKST 72
#define KSTG_B (64 * AKST * 2)          // one K (or V) stage = 9216 B
#define ATTN_SMEM_BYTES (6 * KSTG_B)    // 3 stages x (K + V) = 55296

__global__ __launch_bounds__(128, 2) void attn_kernel() {
    extern __shared__ char smc[];
    const uint32_t sbase = (uint32_t)__cvta_generic_to_shared(smc);
    const uint32_t ks_u = sbase;
    const uint32_t vs_u = sbase + 3 * KSTG_B;

    const int bh = blockIdx.x;                              // 0..63
    const int qt = (int)gridDim.y - 1 - (int)blockIdx.y;    // heavy first
    const int tid = threadIdx.x;
    const int w = tid >> 5;
    const int lane = tid & 31;
    const int g = lane >> 2;
    const int c = lane & 3;

    const size_t hoff = (size_t)bh * NN * DHH;
    const __half* Qg  = g_q + hoff + (size_t)qt * 128 * DHH;
    const __half* Kg0 = g_k + hoff;
    const __half* Vg0 = g_v + hoff;   // [dh][n]

    const int jmax = 2 * qt + 1;

    auto prefetch = [&](int j, int stage) {
        const __half* Kg = Kg0 + (size_t)j * 64 * DHH;
        const __half* Vg = Vg0 + (size_t)j * 64;
        #pragma unroll
        for (int i = 0; i < 4; i++) {
            const int idx = tid + i * 128;        // 0..511
            const int r = idx >> 3, ch = idx & 7;
            const uint32_t off = (uint32_t)((stage * 64 + r) * (AKST * 2) + ch * 16);
            cp16(ks_u + off, &Kg[r * DHH + ch * 8]);
            cp16(vs_u + off, &Vg[(size_t)r * NN + ch * 8]);
        }
        cp_commit();
    };

    // Issue the first two K/V tile prefetches BEFORE loading Q fragments so
    // the cp.async traffic overlaps the ~32 scalar Q loads per thread.
    prefetch(0, 0);
    prefetch(1, 1);   // jmax >= 1 always

    uint32_t aQ[2][4][4];
    #pragma unroll
    for (int mi = 0; mi < 2; mi++) {
        const int r0 = w * 32 + mi * 16 + g, r1 = r0 + 8;
        #pragma unroll
        for (int ks = 0; ks < 4; ks++) {
            aQ[mi][ks][0] = *(const uint32_t*)&Qg[r0 * DHH + ks * 16 + 2 * c];
            aQ[mi][ks][1] = *(const uint32_t*)&Qg[r1 * DHH + ks * 16 + 2 * c];
            aQ[mi][ks][2] = *(const uint32_t*)&Qg[r0 * DHH + ks * 16 + 2 * c + 8];
            aQ[mi][ks][3] = *(const uint32_t*)&Qg[r1 * DHH + ks * 16 + 2 * c + 8];
        }
    }

    float o[2][8][4];
    #pragma unroll
    for (int mi = 0; mi < 2; mi++)
        #pragma unroll
        for (int t = 0; t < 8; t++)
            #pragma unroll
            for (int e = 0; e < 4; e++) o[mi][t][e] = 0.0f;
    float mv[2][2] = { {-INFINITY, -INFINITY}, {-INFINITY, -INFINITY} };
    float lv[2][2] = { {0.0f, 0.0f}, {0.0f, 0.0f} };

    const int row0g = qt * 128 + w * 32;

    const uint32_t bv_rowoff = (uint32_t)((lane & 7) + ((lane & 16) >> 1)) * (AKST * 2);
    const uint32_t bv_chbit  = (uint32_t)((lane >> 3) & 1) * 16;

    int cbuf = 0, nbuf = 2;
    for (int j = 0; j <= jmax; j++) {
        if (j < jmax) asm volatile("cp.async.wait_group 1;\n" ::);
        else          asm volatile("cp.async.wait_group 0;\n" ::);
        __syncthreads();
        if (j + 2 <= jmax) {
            prefetch(j + 2, nbuf);
            nbuf = (nbuf == 2) ? 0 : nbuf + 1;
        }

        const bool skip = (j * 64 > row0g + 31);
        if (!skip) {
            const uint32_t kb_u = ks_u + (uint32_t)(cbuf * KSTG_B) + bv_rowoff + bv_chbit;
            const uint32_t vb_u = vs_u + (uint32_t)(cbuf * KSTG_B) + bv_rowoff + bv_chbit;

            float s[2][8][4];
            #pragma unroll
            for (int mi = 0; mi < 2; mi++)
                #pragma unroll
                for (int t = 0; t < 8; t++)
                    #pragma unroll
                    for (int e = 0; e < 4; e++) s[mi][t][e] = 0.0f;

            #pragma unroll
            for (int ks = 0; ks < 4; ks++) {
                #pragma unroll
                for (int tp = 0; tp < 4; tp++) {
                    uint32_t r0, r1, r2, r3;
                    ldsm4(r0, r1, r2, r3,
                          kb_u + (uint32_t)(tp * 16) * (AKST * 2) + ks * 32);
                    #pragma unroll
                    for (int mi = 0; mi < 2; mi++) {
                        mma_f16(s[mi][2 * tp],     aQ[mi][ks], r0, r1);
                        mma_f16(s[mi][2 * tp + 1], aQ[mi][ks], r2, r3);
                    }
                }
            }

            if (j * 64 + 63 > row0g) {
                #pragma unroll
                for (int mi = 0; mi < 2; mi++) {
                    const int r0 = row0g + mi * 16 + g, r1 = r0 + 8;
                    #pragma unroll
                    for (int t = 0; t < 8; t++) {
                        const int col = j * 64 + t * 8 + 2 * c;
                        if (col     > r0) s[mi][t][0] = -INFINITY;
                        if (col + 1 > r0) s[mi][t][1] = -INFINITY;
                        if (col     > r1) s[mi][t][2] = -INFINITY;
                        if (col + 1 > r1) s[mi][t][3] = -INFINITY;
                    }
                }
            }

            float psum[2][2];
            #pragma unroll
            for (int mi = 0; mi < 2; mi++) {
                float mx0 = -INFINITY, mx1 = -INFINITY;
                #pragma unroll
                for (int t = 0; t < 8; t++) {
                    mx0 = fmaxf(mx0, fmaxf(s[mi][t][0], s[mi][t][1]));
                    mx1 = fmaxf(mx1, fmaxf(s[mi][t][2], s[mi][t][3]));
                }
                mx0 = fmaxf(mx0, __shfl_xor_sync(0xffffffffu, mx0, 1));
                mx0 = fmaxf(mx0, __shfl_xor_sync(0xffffffffu, mx0, 2));
                mx1 = fmaxf(mx1, __shfl_xor_sync(0xffffffffu, mx1, 1));
                mx1 = fmaxf(mx1, __shfl_xor_sync(0xffffffffu, mx1, 2));

                const float mn0 = fmaxf(mv[mi][0], mx0);
                const float mn1 = fmaxf(mv[mi][1], mx1);
                float sum0 = 0.0f, sum1 = 0.0f;
                #pragma unroll
                for (int t = 0; t < 8; t++) {
                    s[mi][t][0] = ex2f(s[mi][t][0] - mn0);
                    s[mi][t][1] = ex2f(s[mi][t][1] - mn0);
                    s[mi][t][2] = ex2f(s[mi][t][2] - mn1);
                    s[mi][t][3] = ex2f(s[mi][t][3] - mn1);
                    sum0 += s[mi][t][0] + s[mi][t][1];
                    sum1 += s[mi][t][2] + s[mi][t][3];
                }
                const float al0 = ex2f(mv[mi][0] - mn0);
                const float al1 = ex2f(mv[mi][1] - mn1);
                lv[mi][0] *= al0;
                lv[mi][1] *= al1;
                psum[mi][0] = sum0;
                psum[mi][1] = sum1;
                mv[mi][0] = mn0; mv[mi][1] = mn1;

                if (!__all_sync(0xffffffffu, (al0 == 1.0f) && (al1 == 1.0f))) {
                    #pragma unroll
                    for (int t = 0; t < 8; t++) {
                        o[mi][t][0] *= al0; o[mi][t][1] *= al0;
                        o[mi][t][2] *= al1; o[mi][t][3] *= al1;
                    }
                }
            }

            #pragma unroll
            for (int ks = 0; ks < 4; ks++) {
                uint32_t a[2][4];
                #pragma unroll
                for (int mi = 0; mi < 2; mi++) {
                    a[mi][0] = h2pack(s[mi][2 * ks][0],     s[mi][2 * ks][1]);
                    a[mi][1] = h2pack(s[mi][2 * ks][2],     s[mi][2 * ks][3]);
                    a[mi][2] = h2pack(s[mi][2 * ks + 1][0], s[mi][2 * ks + 1][1]);
                    a[mi][3] = h2pack(s[mi][2 * ks + 1][2], s[mi][2 * ks + 1][3]);
                }
                #pragma unroll
                for (int tp = 0; tp < 4; tp++) {
                    uint32_t r0, r1, r2, r3;
                    ldsm4(r0, r1, r2, r3,
                          vb_u + (uint32_t)(tp * 16) * (AKST * 2) + ks * 32);
                    #pragma unroll
                    for (int mi = 0; mi < 2; mi++) {
                        mma_f16(o[mi][2 * tp],     a[mi], r0, r1);
                        mma_f16(o[mi][2 * tp + 1], a[mi], r2, r3);
                    }
                }
            }

            #pragma unroll
            for (int mi = 0; mi < 2; mi++) {
                float sum0 = psum[mi][0], sum1 = psum[mi][1];
                sum0 += __shfl_xor_sync(0xffffffffu, sum0, 1);
                sum0 += __shfl_xor_sync(0xffffffffu, sum0, 2);
                sum1 += __shfl_xor_sync(0xffffffffu, sum1, 1);
                sum1 += __shfl_xor_sync(0xffffffffu, sum1, 2);
                lv[mi][0] += sum0;
                lv[mi][1] += sum1;
            }
        }
        cbuf = (cbuf == 2) ? 0 : cbuf + 1;
    }

    const int b = bh >> 4, h = bh & 15;
    __half* Og = g_ao + ((size_t)(b * NN + qt * 128)) * DD + h * DHH;
    #pragma unroll
    for (int mi = 0; mi < 2; mi++) {
        const float i0 = 1.0f / lv[mi][0], i1 = 1.0f / lv[mi][1];
        const int r0 = w * 32 + mi * 16 + g, r1 = r0 + 8;
        #pragma unroll
        for (int t = 0; t < 8; t++) {
            *(uint32_t*)&Og[(size_t)r0 * DD + t * 8 + 2 * c] =
                h2pack(o[mi][t][0] * i0, o[mi][t][1] * i0);
            *(uint32_t*)&Og[(size_t)r1 * DD + t * 8 + 2 * c] =
                h2pack(o[mi][t][2] * i1, o[mi][t][3] * i1);
        }
    }
}

// ============================================================================
// Launch
// ============================================================================
extern "C" void kernel_launch(void* const* d_in, const int* in_sizes, int n_in,
                              void* d_out, int out_size) {
    (void)in_sizes; (void)n_in; (void)out_size;
    const float* x   = (const float*)d_in[0];
    const float* g   = (const float*)d_in[1];
    const float* Wq  = (const float*)d_in[2];
    const float* Wkv = (const float*)d_in[3];
    const float* Wo  = (const float*)d_in[4];
    float* out = (float*)d_out;

    cudaFuncSetAttribute(gemm_mma<0>, cudaFuncAttributeMaxDynamicSharedMemorySize,
                         GEMM_SMEM_BYTES);
    cudaFuncSetAttribute(gemm_mma<1>, cudaFuncAttributeMaxDynamicSharedMemorySize,
                         GEMM_SMEM_BYTES);
    cudaFuncSetAttribute(attn_kernel, cudaFuncAttributeMaxDynamicSharedMemorySize,
                         ATTN_SMEM_BYTES);

    // 0) Fused prep: weight transpose+round (fp16, vectorized) + LayerNorm
    prep_kernel<<<2048, 256>>>(x, g, Wq, Wkv, Wo);

    // 1) Fused QKV projection (M=8192, N=3072)
    gemm_mma<0><<<dim3(24, 64), 128, GEMM_SMEM_BYTES>>>(nullptr);

    // 2) Causal flash attention (128-q-row CTAs, 128 threads, 2 CTAs/SM)
    attn_kernel<<<dim3(BB * HH, 16), 128, ATTN_SMEM_BYTES>>>();

    // 3) Output projection (M=8192, N=1024) -> fp32 out
    gemm_mma<1><<<dim3(8, 64), 128, GEMM_SMEM_BYTES>>>(out);
}